// round 9
// baseline (speedup 1.0000x reference)
#include <cuda_runtime.h>
#include <cuda_fp16.h>
#include <cstdint>

#define B_DIM   512
#define IN_DIM  4096
#define OUT_DIM 11008

#define BM 128
#define BN 128
#define BK 32
#define NK (IN_DIM / BK)   // 128 k-chunks
#define STAGES 4
#define THREADS 256

#define ROWPAD 80                       // 64B data + 16B pad per row (bank-conflict-free)
#define TILE_B (128 * ROWPAD)           // 10240 B per tile
#define STAGE_B (2 * TILE_B)            // 20480 B per stage (A, B)
#define SMEM_TOTAL (STAGES * STAGE_B)   // 81920 B

#define NCHUNK 4

// ---------------- device scratch (static device arrays are allowed) ----------------
__device__ __half g_w[(size_t)OUT_DIM * IN_DIM];
__device__ __half g_x[(size_t)B_DIM * IN_DIM];

// ---------------- PTX helpers (plain sm_80+ features only) -------------------------
__device__ __forceinline__ uint32_t smem_u32(const void* p) {
    uint32_t a;
    asm("{ .reg .u64 t; cvta.to.shared.u64 t, %1; cvt.u32.u64 %0, t; }" : "=r"(a) : "l"(p));
    return a;
}

__device__ __forceinline__ void cp16(uint32_t s, const void* g) {
    asm volatile("cp.async.cg.shared.global [%0], [%1], 16;" :: "r"(s), "l"(g));
}
__device__ __forceinline__ void cp_commit() {
    asm volatile("cp.async.commit_group;" ::: "memory");
}
template <int N>
__device__ __forceinline__ void cp_wait() {
    asm volatile("cp.async.wait_group %0;" :: "n"(N) : "memory");
}

__device__ __forceinline__ void ldsm4(uint32_t* r, uint32_t addr) {
    asm volatile("ldmatrix.sync.aligned.m8n8.x4.shared.b16 {%0,%1,%2,%3}, [%4];"
                 : "=r"(r[0]), "=r"(r[1]), "=r"(r[2]), "=r"(r[3]) : "r"(addr));
}

__device__ __forceinline__ void mma_fp16(float* d, const uint32_t* a, const uint32_t* b) {
    asm volatile("mma.sync.aligned.m16n8k16.row.col.f32.f16.f16.f32 "
                 "{%0,%1,%2,%3}, {%4,%5,%6,%7}, {%8,%9}, {%0,%1,%2,%3};"
                 : "+f"(d[0]), "+f"(d[1]), "+f"(d[2]), "+f"(d[3])
                 : "r"(a[0]), "r"(a[1]), "r"(a[2]), "r"(a[3]), "r"(b[0]), "r"(b[1]));
}

// ---------------- Kernel 1: dequant W rows [beg4, end4) -> fp16 (exp LUT) ----------
__global__ void dequant_kernel(const int* __restrict__ stored, const int* __restrict__ sgn,
                               const float* __restrict__ lmin_p, const float* __restrict__ lmax_p,
                               size_t beg4, size_t end4) {
    __shared__ unsigned short lut[256];
    float lmin = *lmin_p;
    float kf = (*lmax_p - lmin) * (1.0f / 254.0f);
    for (int s = threadIdx.x; s < 256; s += blockDim.x) {
        float w = expf(lmin + (float)(255 - s) * kf);
        lut[s] = __half_as_ushort(__float2half_rn(w));
    }
    __syncthreads();

    const int4* st4 = (const int4*)stored;
    const int4* sg4 = (const int4*)sgn;
    ushort4* w4 = (ushort4*)g_w;
    for (size_t i = beg4 + (size_t)blockIdx.x * blockDim.x + threadIdx.x; i < end4;
         i += (size_t)gridDim.x * blockDim.x) {
        int4 s = st4[i];
        int4 g = sg4[i];
        unsigned short h0 = lut[s.x & 255] ^ (g.x < 0 ? 0x8000u : 0u);
        unsigned short h1 = lut[s.y & 255] ^ (g.y < 0 ? 0x8000u : 0u);
        unsigned short h2 = lut[s.z & 255] ^ (g.z < 0 ? 0x8000u : 0u);
        unsigned short h3 = lut[s.w & 255] ^ (g.w < 0 ? 0x8000u : 0u);
        w4[i] = make_ushort4(h0, h1, h2, h3);
    }
}

// ---------------- Kernel 2: convert x -> fp16 --------------------------------------
__global__ void xconv_kernel(const float* __restrict__ x) {
    const float4* x4 = (const float4*)x;
    ushort4* xh = (ushort4*)g_x;
    size_t n4 = (size_t)B_DIM * IN_DIM / 4;
    for (size_t i = (size_t)blockIdx.x * blockDim.x + threadIdx.x; i < n4;
         i += (size_t)gridDim.x * blockDim.x) {
        float4 v = x4[i];
        xh[i] = make_ushort4(__half_as_ushort(__float2half_rn(v.x)),
                             __half_as_ushort(__float2half_rn(v.y)),
                             __half_as_ushort(__float2half_rn(v.z)),
                             __half_as_ushort(__float2half_rn(v.w)));
    }
}

// ---------------- Kernel 3: pipelined mma.sync fp16 GEMM + epilogue ----------------
__global__ void __launch_bounds__(THREADS, 1)
gemm_kernel(float* __restrict__ out, const float* __restrict__ scale,
            const float* __restrict__ bias, int nb0) {
    extern __shared__ char smem[];
    const uint32_t sb = smem_u32(smem);
    const int tid = threadIdx.x;
    const int lane = tid & 31, wid = tid >> 5;
    const int nb = (nb0 + blockIdx.x) * BN, mb = blockIdx.y * BM;
    const int warp_m = (wid & 3) * 32, warp_n = (wid >> 2) * 64;

    const char* gA = (const char*)(g_x + (size_t)mb * IN_DIM);
    const char* gB = (const char*)(g_w + (size_t)nb * IN_DIM);

    // cp.async mapping: thread -> (row = tid/2, 32B half = tid%2); 2x16B per tile
    const int lrow = tid >> 1;
    const int lc = (tid & 1) * 32;

    // ldmatrix base offsets
    const uint32_t a_off = (uint32_t)(warp_m + (lane & 15)) * ROWPAD + ((lane >> 4) * 16);
    const uint32_t b_off =
        (uint32_t)(warp_n + (lane & 7) + ((lane >> 4) & 1) * 8) * ROWPAD + (((lane >> 3) & 1) * 16);

    float acc[2][8][4];
#pragma unroll
    for (int i = 0; i < 2; i++)
#pragma unroll
        for (int j = 0; j < 8; j++)
#pragma unroll
            for (int c = 0; c < 4; c++) acc[i][j][c] = 0.0f;

    auto load_stage = [&](int s, int k) {
        size_t go = (size_t)lrow * (IN_DIM * 2) + (size_t)k * (BK * 2) + lc;
        uint32_t so = sb + s * STAGE_B + (uint32_t)lrow * ROWPAD + lc;
        cp16(so, gA + go);
        cp16(so + 16, gA + go + 16);
        cp16(so + TILE_B, gB + go);
        cp16(so + TILE_B + 16, gB + go + 16);
    };

    auto compute_stage = [&](int s) {
        uint32_t st = sb + s * STAGE_B;
        uint32_t aA = st + a_off;
        uint32_t bB = st + TILE_B + b_off;
#pragma unroll
        for (int s16 = 0; s16 < 2; s16++) {
            uint32_t kb = s16 * 32;
            uint32_t a[2][4];
            ldsm4(a[0], aA + kb);
            ldsm4(a[1], aA + 16 * ROWPAD + kb);
#pragma unroll
            for (int nblk = 0; nblk < 4; nblk++) {
                uint32_t b[4];
                ldsm4(b, bB + nblk * 16 * ROWPAD + kb);
#pragma unroll
                for (int mt = 0; mt < 2; mt++) {
                    mma_fp16(acc[mt][2 * nblk], a[mt], b);
                    mma_fp16(acc[mt][2 * nblk + 1], a[mt], b + 2);
                }
            }
        }
    };

    // prologue: fill STAGES-1 stages
#pragma unroll
    for (int s = 0; s < STAGES - 1; s++) {
        load_stage(s, s);
        cp_commit();
    }

    int rs = 0, ws = STAGES - 1;
    for (int k = 0; k < NK; k++) {
        cp_wait<STAGES - 2>();
        __syncthreads();
        compute_stage(rs);
        if (k + STAGES - 1 < NK) load_stage(ws, k + STAGES - 1);
        cp_commit();
        rs = (rs + 1) & (STAGES - 1);
        ws = (ws + 1) & (STAGES - 1);
    }

    // epilogue: (acc + bias) * scale, float2 stores
#pragma unroll
    for (int nf = 0; nf < 8; nf++) {
        int n0 = nb + warp_n + nf * 8 + 2 * (lane & 3);
        float s0 = scale[n0], s1 = scale[n0 + 1];
        float b0 = bias[n0], b1 = bias[n0 + 1];
#pragma unroll
        for (int mt = 0; mt < 2; mt++) {
            int m0 = mb + warp_m + mt * 16 + (lane >> 2);
            float* p0 = out + (size_t)m0 * OUT_DIM + n0;
            float2 v0;
            v0.x = (acc[mt][nf][0] + b0) * s0;
            v0.y = (acc[mt][nf][1] + b1) * s1;
            *(float2*)p0 = v0;
            float2 v1;
            v1.x = (acc[mt][nf][2] + b0) * s0;
            v1.y = (acc[mt][nf][3] + b1) * s1;
            *(float2*)(p0 + 8 * OUT_DIM) = v1;
        }
    }
}

// ---------------- stream/event setup at static init (pre-checkpoint) ---------------
struct OvInit {
    cudaStream_t s1;
    cudaEvent_t evF, evJ, evD[NCHUNK];
    OvInit() {
        cudaStreamCreateWithFlags(&s1, cudaStreamNonBlocking);
        cudaEventCreateWithFlags(&evF, cudaEventDisableTiming);
        cudaEventCreateWithFlags(&evJ, cudaEventDisableTiming);
        for (int i = 0; i < NCHUNK; i++) cudaEventCreateWithFlags(&evD[i], cudaEventDisableTiming);
        cudaFuncSetAttribute(gemm_kernel, cudaFuncAttributeMaxDynamicSharedMemorySize, SMEM_TOTAL);
        // force lazy resource allocation now, outside the harness checkpoint windows
        cudaEventRecord(evJ, s1);
        cudaStreamSynchronize(s1);
        cudaEventRecord(evF, 0);
        cudaStreamSynchronize(0);
    }
};
static OvInit g_ov;

// N col-block chunking: 86 blocks -> 22/22/21/21
static const int chunk_blk[NCHUNK] = {22, 22, 21, 21};
static const int chunk_nb0[NCHUNK] = {0, 22, 44, 65};

// ---------------- launch ----------------
extern "C" void kernel_launch(void* const* d_in, const int* in_sizes, int n_in,
                              void* d_out, int out_size) {
    const float* x      = (const float*)d_in[0];
    const int*   stored = (const int*)d_in[1];
    const int*   sgn    = (const int*)d_in[2];
    const float* lmin   = (const float*)d_in[3];
    const float* lmax   = (const float*)d_in[4];
    const float* scale  = (const float*)d_in[5];
    const float* bias   = (const float*)d_in[6];
    float* out = (float*)d_out;

    // fork side stream from the capture (default) stream
    cudaEventRecord(g_ov.evF, 0);
    cudaStreamWaitEvent(g_ov.s1, g_ov.evF, 0);

    // x conversion on the side stream (independent of dequant)
    xconv_kernel<<<512, 256, 0, g_ov.s1>>>(x);

    // dequant chunks on the capture stream, each signaling an event
    for (int c = 0; c < NCHUNK; c++) {
        size_t beg4 = (size_t)chunk_nb0[c] * BN * (IN_DIM / 4);
        size_t end4 = beg4 + (size_t)chunk_blk[c] * BN * (IN_DIM / 4);
        dequant_kernel<<<1024, 256>>>(stored, sgn, lmin, lmax, beg4, end4);
        cudaEventRecord(g_ov.evD[c], 0);
    }

    // GEMM chunks on the side stream, each gated on its dequant chunk
    for (int c = 0; c < NCHUNK; c++) {
        cudaStreamWaitEvent(g_ov.s1, g_ov.evD[c], 0);
        dim3 grid(chunk_blk[c], B_DIM / BM);
        gemm_kernel<<<grid, THREADS, SMEM_TOTAL, g_ov.s1>>>(out, scale, bias, chunk_nb0[c]);
    }

    // join side stream back into the capture stream
    cudaEventRecord(g_ov.evJ, g_ov.s1);
    cudaStreamWaitEvent(0, g_ov.evJ, 0);
}

// round 11
// speedup vs baseline: 1.2423x; 1.2423x over previous
#include <cuda_runtime.h>
#include <cuda_fp16.h>
#include <cstdint>

#define B_DIM   512
#define IN_DIM  4096
#define OUT_DIM 11008

#define BM 128
#define BN 128
#define BK 32
#define NK (IN_DIM / BK)   // 128 k-chunks
#define STAGES 4
#define THREADS 256

#define ROWPAD 80                       // 64B data + 16B pad per row (bank-conflict-free)
#define TILE_B (128 * ROWPAD)           // 10240 B per tile
#define STAGE_B (2 * TILE_B)            // 20480 B per stage (A, B)
#define SMEM_TOTAL (STAGES * STAGE_B)   // 81920 B -> 2 CTAs/SM = 160KB <= 228KB

// ---------------- device scratch (static device arrays are allowed) ----------------
__device__ __half g_w[(size_t)OUT_DIM * IN_DIM];
__device__ __half g_x[(size_t)B_DIM * IN_DIM];

// ---------------- PTX helpers (plain sm_80+ features only) -------------------------
__device__ __forceinline__ uint32_t smem_u32(const void* p) {
    uint32_t a;
    asm("{ .reg .u64 t; cvta.to.shared.u64 t, %1; cvt.u32.u64 %0, t; }" : "=r"(a) : "l"(p));
    return a;
}

__device__ __forceinline__ void cp16(uint32_t s, const void* g) {
    asm volatile("cp.async.cg.shared.global [%0], [%1], 16;" :: "r"(s), "l"(g));
}
__device__ __forceinline__ void cp_commit() {
    asm volatile("cp.async.commit_group;" ::: "memory");
}
template <int N>
__device__ __forceinline__ void cp_wait() {
    asm volatile("cp.async.wait_group %0;" :: "n"(N) : "memory");
}

__device__ __forceinline__ void ldsm4(uint32_t* r, uint32_t addr) {
    asm volatile("ldmatrix.sync.aligned.m8n8.x4.shared.b16 {%0,%1,%2,%3}, [%4];"
                 : "=r"(r[0]), "=r"(r[1]), "=r"(r[2]), "=r"(r[3]) : "r"(addr));
}

__device__ __forceinline__ void mma_fp16(float* d, const uint32_t* a, const uint32_t* b) {
    asm volatile("mma.sync.aligned.m16n8k16.row.col.f32.f16.f16.f32 "
                 "{%0,%1,%2,%3}, {%4,%5,%6,%7}, {%8,%9}, {%0,%1,%2,%3};"
                 : "+f"(d[0]), "+f"(d[1]), "+f"(d[2]), "+f"(d[3])
                 : "r"(a[0]), "r"(a[1]), "r"(a[2]), "r"(a[3]), "r"(b[0]), "r"(b[1]));
}

// ---------------- Kernel 1: dequant W -> single fp16 (256-entry exp LUT) -----------
__global__ void dequant_kernel(const int* __restrict__ stored, const int* __restrict__ sgn,
                               const float* __restrict__ lmin_p, const float* __restrict__ lmax_p) {
    __shared__ unsigned short lut[256];
    float lmin = *lmin_p;
    float kf = (*lmax_p - lmin) * (1.0f / 254.0f);
    for (int s = threadIdx.x; s < 256; s += blockDim.x) {
        float w = expf(lmin + (float)(255 - s) * kf);
        lut[s] = __half_as_ushort(__float2half_rn(w));
    }
    __syncthreads();

    const int4* st4 = (const int4*)stored;
    const int4* sg4 = (const int4*)sgn;
    ushort4* w4 = (ushort4*)g_w;
    size_t nq = (size_t)OUT_DIM * IN_DIM / 4;
    for (size_t i = (size_t)blockIdx.x * blockDim.x + threadIdx.x; i < nq;
         i += (size_t)gridDim.x * blockDim.x) {
        int4 s = st4[i];
        int4 g = sg4[i];
        unsigned short h0 = lut[s.x & 255] ^ (g.x < 0 ? 0x8000u : 0u);
        unsigned short h1 = lut[s.y & 255] ^ (g.y < 0 ? 0x8000u : 0u);
        unsigned short h2 = lut[s.z & 255] ^ (g.z < 0 ? 0x8000u : 0u);
        unsigned short h3 = lut[s.w & 255] ^ (g.w < 0 ? 0x8000u : 0u);
        w4[i] = make_ushort4(h0, h1, h2, h3);
    }
}

// ---------------- Kernel 2: convert x -> fp16 --------------------------------------
__global__ void xconv_kernel(const float* __restrict__ x) {
    const float4* x4 = (const float4*)x;
    ushort4* xh = (ushort4*)g_x;
    size_t n4 = (size_t)B_DIM * IN_DIM / 4;
    for (size_t i = (size_t)blockIdx.x * blockDim.x + threadIdx.x; i < n4;
         i += (size_t)gridDim.x * blockDim.x) {
        float4 v = x4[i];
        xh[i] = make_ushort4(__half_as_ushort(__float2half_rn(v.x)),
                             __half_as_ushort(__float2half_rn(v.y)),
                             __half_as_ushort(__float2half_rn(v.z)),
                             __half_as_ushort(__float2half_rn(v.w)));
    }
}

// ---------------- Kernel 3: pipelined mma.sync fp16 GEMM + epilogue ----------------
// __launch_bounds__(256, 2): cap regs at 128/thread so 2 CTAs co-reside per SM,
// eliminating the 2.32-waves-in-3 quantization of the 344-CTA grid.
__global__ void __launch_bounds__(THREADS, 2)
gemm_kernel(float* __restrict__ out, const float* __restrict__ scale,
            const float* __restrict__ bias) {
    extern __shared__ char smem[];
    const uint32_t sb = smem_u32(smem);
    const int tid = threadIdx.x;
    const int lane = tid & 31, wid = tid >> 5;
    const int nb = blockIdx.x * BN, mb = blockIdx.y * BM;
    const int warp_m = (wid & 3) * 32, warp_n = (wid >> 2) * 64;

    const char* gA = (const char*)(g_x + (size_t)mb * IN_DIM);
    const char* gB = (const char*)(g_w + (size_t)nb * IN_DIM);

    // cp.async mapping: thread -> (row = tid/2, 32B half = tid%2); 2x16B per tile
    const int lrow = tid >> 1;
    const int lc = (tid & 1) * 32;

    // ldmatrix base offsets
    const uint32_t a_off = (uint32_t)(warp_m + (lane & 15)) * ROWPAD + ((lane >> 4) * 16);
    const uint32_t b_off =
        (uint32_t)(warp_n + (lane & 7) + ((lane >> 4) & 1) * 8) * ROWPAD + (((lane >> 3) & 1) * 16);

    float acc[2][8][4];
#pragma unroll
    for (int i = 0; i < 2; i++)
#pragma unroll
        for (int j = 0; j < 8; j++)
#pragma unroll
            for (int c = 0; c < 4; c++) acc[i][j][c] = 0.0f;

    auto load_stage = [&](int s, int k) {
        size_t go = (size_t)lrow * (IN_DIM * 2) + (size_t)k * (BK * 2) + lc;
        uint32_t so = sb + s * STAGE_B + (uint32_t)lrow * ROWPAD + lc;
        cp16(so, gA + go);
        cp16(so + 16, gA + go + 16);
        cp16(so + TILE_B, gB + go);
        cp16(so + TILE_B + 16, gB + go + 16);
    };

    auto compute_stage = [&](int s) {
        uint32_t st = sb + s * STAGE_B;
        uint32_t aA = st + a_off;
        uint32_t bB = st + TILE_B + b_off;
#pragma unroll
        for (int s16 = 0; s16 < 2; s16++) {
            uint32_t kb = s16 * 32;
            uint32_t a[2][4];
            ldsm4(a[0], aA + kb);
            ldsm4(a[1], aA + 16 * ROWPAD + kb);
#pragma unroll
            for (int nblk = 0; nblk < 4; nblk++) {
                uint32_t b[4];
                ldsm4(b, bB + nblk * 16 * ROWPAD + kb);
#pragma unroll
                for (int mt = 0; mt < 2; mt++) {
                    mma_fp16(acc[mt][2 * nblk], a[mt], b);
                    mma_fp16(acc[mt][2 * nblk + 1], a[mt], b + 2);
                }
            }
        }
    };

    // prologue: fill STAGES-1 stages
#pragma unroll
    for (int s = 0; s < STAGES - 1; s++) {
        load_stage(s, s);
        cp_commit();
    }

    int rs = 0, ws = STAGES - 1;
    for (int k = 0; k < NK; k++) {
        cp_wait<STAGES - 2>();
        __syncthreads();
        compute_stage(rs);
        if (k + STAGES - 1 < NK) load_stage(ws, k + STAGES - 1);
        cp_commit();
        rs = (rs + 1) & (STAGES - 1);
        ws = (ws + 1) & (STAGES - 1);
    }

    // epilogue: (acc + bias) * scale, float2 stores
#pragma unroll
    for (int nf = 0; nf < 8; nf++) {
        int n0 = nb + warp_n + nf * 8 + 2 * (lane & 3);
        float s0 = scale[n0], s1 = scale[n0 + 1];
        float b0 = bias[n0], b1 = bias[n0 + 1];
#pragma unroll
        for (int mt = 0; mt < 2; mt++) {
            int m0 = mb + warp_m + mt * 16 + (lane >> 2);
            float* p0 = out + (size_t)m0 * OUT_DIM + n0;
            float2 v0;
            v0.x = (acc[mt][nf][0] + b0) * s0;
            v0.y = (acc[mt][nf][1] + b1) * s1;
            *(float2*)p0 = v0;
            float2 v1;
            v1.x = (acc[mt][nf][2] + b0) * s0;
            v1.y = (acc[mt][nf][3] + b1) * s1;
            *(float2*)(p0 + 8 * OUT_DIM) = v1;
        }
    }
}

// ---------------- launch ----------------
extern "C" void kernel_launch(void* const* d_in, const int* in_sizes, int n_in,
                              void* d_out, int out_size) {
    const float* x      = (const float*)d_in[0];
    const int*   stored = (const int*)d_in[1];
    const int*   sgn    = (const int*)d_in[2];
    const float* lmin   = (const float*)d_in[3];
    const float* lmax   = (const float*)d_in[4];
    const float* scale  = (const float*)d_in[5];
    const float* bias   = (const float*)d_in[6];
    float* out = (float*)d_out;

    dequant_kernel<<<4096, 256>>>(stored, sgn, lmin, lmax);
    xconv_kernel<<<512, 256>>>(x);

    static int smem_set = 0;
    if (!smem_set) {
        cudaFuncSetAttribute(gemm_kernel, cudaFuncAttributeMaxDynamicSharedMemorySize, SMEM_TOTAL);
        smem_set = 1;
    }
    dim3 grid(OUT_DIM / BN, B_DIM / BM);   // (86, 4)
    gemm_kernel<<<grid, THREADS, SMEM_TOTAL>>>(out, scale, bias);
}

// round 12
// speedup vs baseline: 1.3166x; 1.0598x over previous
#include <cuda_runtime.h>
#include <cuda_fp16.h>
#include <cstdint>

#define B_DIM   512
#define IN_DIM  4096
#define OUT_DIM 11008

#define BM 64
#define BN 128
#define BK 32
#define NK (IN_DIM / BK)   // 128 k-chunks
#define STAGES 4
#define THREADS 128

#define ROWPAD 80                        // 64B data + 16B pad per row (bank-conflict-free)
#define TILE_A_B (BM * ROWPAD)           // 5120 B
#define TILE_B_B (BN * ROWPAD)           // 10240 B
#define STAGE_B (TILE_A_B + TILE_B_B)    // 15360 B per stage
#define SMEM_TOTAL (STAGES * STAGE_B)    // 61440 B -> 3 CTAs/SM = 180KB <= 228KB

// ---------------- device scratch (static device arrays are allowed) ----------------
__device__ __half g_w[(size_t)OUT_DIM * IN_DIM];
__device__ __half g_x[(size_t)B_DIM * IN_DIM];

// ---------------- PTX helpers (plain sm_80+ features only) -------------------------
__device__ __forceinline__ uint32_t smem_u32(const void* p) {
    uint32_t a;
    asm("{ .reg .u64 t; cvta.to.shared.u64 t, %1; cvt.u32.u64 %0, t; }" : "=r"(a) : "l"(p));
    return a;
}

__device__ __forceinline__ void cp16(uint32_t s, const void* g) {
    asm volatile("cp.async.cg.shared.global [%0], [%1], 16;" :: "r"(s), "l"(g));
}
__device__ __forceinline__ void cp_commit() {
    asm volatile("cp.async.commit_group;" ::: "memory");
}
template <int N>
__device__ __forceinline__ void cp_wait() {
    asm volatile("cp.async.wait_group %0;" :: "n"(N) : "memory");
}

__device__ __forceinline__ void ldsm4(uint32_t* r, uint32_t addr) {
    asm volatile("ldmatrix.sync.aligned.m8n8.x4.shared.b16 {%0,%1,%2,%3}, [%4];"
                 : "=r"(r[0]), "=r"(r[1]), "=r"(r[2]), "=r"(r[3]) : "r"(addr));
}

__device__ __forceinline__ void mma_fp16(float* d, const uint32_t* a, const uint32_t* b) {
    asm volatile("mma.sync.aligned.m16n8k16.row.col.f32.f16.f16.f32 "
                 "{%0,%1,%2,%3}, {%4,%5,%6,%7}, {%8,%9}, {%0,%1,%2,%3};"
                 : "+f"(d[0]), "+f"(d[1]), "+f"(d[2]), "+f"(d[3])
                 : "r"(a[0]), "r"(a[1]), "r"(a[2]), "r"(a[3]), "r"(b[0]), "r"(b[1]));
}

// ---------------- Kernel 1: dequant W -> single fp16 (256-entry exp LUT) -----------
__global__ void dequant_kernel(const int* __restrict__ stored, const int* __restrict__ sgn,
                               const float* __restrict__ lmin_p, const float* __restrict__ lmax_p) {
    __shared__ unsigned short lut[256];
    float lmin = *lmin_p;
    float kf = (*lmax_p - lmin) * (1.0f / 254.0f);
    for (int s = threadIdx.x; s < 256; s += blockDim.x) {
        float w = expf(lmin + (float)(255 - s) * kf);
        lut[s] = __half_as_ushort(__float2half_rn(w));
    }
    __syncthreads();

    const int4* st4 = (const int4*)stored;
    const int4* sg4 = (const int4*)sgn;
    ushort4* w4 = (ushort4*)g_w;
    size_t nq = (size_t)OUT_DIM * IN_DIM / 4;
    for (size_t i = (size_t)blockIdx.x * blockDim.x + threadIdx.x; i < nq;
         i += (size_t)gridDim.x * blockDim.x) {
        int4 s = st4[i];
        int4 g = sg4[i];
        unsigned short h0 = lut[s.x & 255] ^ (g.x < 0 ? 0x8000u : 0u);
        unsigned short h1 = lut[s.y & 255] ^ (g.y < 0 ? 0x8000u : 0u);
        unsigned short h2 = lut[s.z & 255] ^ (g.z < 0 ? 0x8000u : 0u);
        unsigned short h3 = lut[s.w & 255] ^ (g.w < 0 ? 0x8000u : 0u);
        w4[i] = make_ushort4(h0, h1, h2, h3);
    }
}

// ---------------- Kernel 2: convert x -> fp16 --------------------------------------
__global__ void xconv_kernel(const float* __restrict__ x) {
    const float4* x4 = (const float4*)x;
    ushort4* xh = (ushort4*)g_x;
    size_t n4 = (size_t)B_DIM * IN_DIM / 4;
    for (size_t i = (size_t)blockIdx.x * blockDim.x + threadIdx.x; i < n4;
         i += (size_t)gridDim.x * blockDim.x) {
        float4 v = x4[i];
        xh[i] = make_ushort4(__half_as_ushort(__float2half_rn(v.x)),
                             __half_as_ushort(__float2half_rn(v.y)),
                             __half_as_ushort(__float2half_rn(v.z)),
                             __half_as_ushort(__float2half_rn(v.w)));
    }
}

// ---------------- Kernel 3: pipelined mma.sync fp16 GEMM + epilogue ----------------
// BM=64 / 128 threads / 4 warps (2 along M x 2 along N, each the proven 32x64 warp
// tile). 688 CTAs at 3 CTAs/SM: per-SM load max/mean = 5/4.65 (7.5% straggler
// stretch vs 29% with BM=128).
__global__ void __launch_bounds__(THREADS, 3)
gemm_kernel(float* __restrict__ out, const float* __restrict__ scale,
            const float* __restrict__ bias) {
    extern __shared__ char smem[];
    const uint32_t sb = smem_u32(smem);
    const int tid = threadIdx.x;
    const int lane = tid & 31, wid = tid >> 5;
    const int nb = blockIdx.x * BN, mb = blockIdx.y * BM;
    const int warp_m = (wid & 1) * 32, warp_n = (wid >> 1) * 64;

    const char* gA = (const char*)(g_x + (size_t)mb * IN_DIM);
    const char* gB = (const char*)(g_w + (size_t)nb * IN_DIM);

    // ldmatrix base offsets (same warp-tile math as the proven BM=128 kernel)
    const uint32_t a_off = (uint32_t)(warp_m + (lane & 15)) * ROWPAD + ((lane >> 4) * 16);
    const uint32_t b_off =
        (uint32_t)(warp_n + (lane & 7) + ((lane >> 4) & 1) * 8) * ROWPAD + (((lane >> 3) & 1) * 16);

    float acc[2][8][4];
#pragma unroll
    for (int i = 0; i < 2; i++)
#pragma unroll
        for (int j = 0; j < 8; j++)
#pragma unroll
            for (int c = 0; c < 4; c++) acc[i][j][c] = 0.0f;

    // cp.async: stage = A(64 rows) + B(128 rows), 4x16B chunks per row.
    // A: 256 chunks -> 2 per thread; B: 512 chunks -> 4 per thread.
    auto load_stage = [&](int s, int k) {
        uint32_t st = sb + s * STAGE_B;
        size_t kbyte = (size_t)k * (BK * 2);
#pragma unroll
        for (int i = 0; i < 2; i++) {
            int idx = tid + i * THREADS;          // 0..255
            int row = idx >> 2, c16 = (idx & 3) * 16;
            cp16(st + (uint32_t)row * ROWPAD + c16,
                 gA + (size_t)row * (IN_DIM * 2) + kbyte + c16);
        }
#pragma unroll
        for (int i = 0; i < 4; i++) {
            int idx = tid + i * THREADS;          // 0..511
            int row = idx >> 2, c16 = (idx & 3) * 16;
            cp16(st + TILE_A_B + (uint32_t)row * ROWPAD + c16,
                 gB + (size_t)row * (IN_DIM * 2) + kbyte + c16);
        }
    };

    auto compute_stage = [&](int s) {
        uint32_t st = sb + s * STAGE_B;
        uint32_t aA = st + a_off;
        uint32_t bB = st + TILE_A_B + b_off;
#pragma unroll
        for (int s16 = 0; s16 < 2; s16++) {
            uint32_t kb = s16 * 32;
            uint32_t a[2][4];
            ldsm4(a[0], aA + kb);
            ldsm4(a[1], aA + 16 * ROWPAD + kb);
#pragma unroll
            for (int nblk = 0; nblk < 4; nblk++) {
                uint32_t b[4];
                ldsm4(b, bB + nblk * 16 * ROWPAD + kb);
#pragma unroll
                for (int mt = 0; mt < 2; mt++) {
                    mma_fp16(acc[mt][2 * nblk], a[mt], b);
                    mma_fp16(acc[mt][2 * nblk + 1], a[mt], b + 2);
                }
            }
        }
    };

    // prologue: fill STAGES-1 stages
#pragma unroll
    for (int s = 0; s < STAGES - 1; s++) {
        load_stage(s, s);
        cp_commit();
    }

    int rs = 0, ws = STAGES - 1;
    for (int k = 0; k < NK; k++) {
        cp_wait<STAGES - 2>();
        __syncthreads();
        compute_stage(rs);
        if (k + STAGES - 1 < NK) load_stage(ws, k + STAGES - 1);
        cp_commit();
        rs = (rs + 1) & (STAGES - 1);
        ws = (ws + 1) & (STAGES - 1);
    }

    // epilogue: (acc + bias) * scale, float2 stores
#pragma unroll
    for (int nf = 0; nf < 8; nf++) {
        int n0 = nb + warp_n + nf * 8 + 2 * (lane & 3);
        float s0 = scale[n0], s1 = scale[n0 + 1];
        float b0 = bias[n0], b1 = bias[n0 + 1];
#pragma unroll
        for (int mt = 0; mt < 2; mt++) {
            int m0 = mb + warp_m + mt * 16 + (lane >> 2);
            float* p0 = out + (size_t)m0 * OUT_DIM + n0;
            float2 v0;
            v0.x = (acc[mt][nf][0] + b0) * s0;
            v0.y = (acc[mt][nf][1] + b1) * s1;
            *(float2*)p0 = v0;
            float2 v1;
            v1.x = (acc[mt][nf][2] + b0) * s0;
            v1.y = (acc[mt][nf][3] + b1) * s1;
            *(float2*)(p0 + 8 * OUT_DIM) = v1;
        }
    }
}

// ---------------- launch ----------------
extern "C" void kernel_launch(void* const* d_in, const int* in_sizes, int n_in,
                              void* d_out, int out_size) {
    const float* x      = (const float*)d_in[0];
    const int*   stored = (const int*)d_in[1];
    const int*   sgn    = (const int*)d_in[2];
    const float* lmin   = (const float*)d_in[3];
    const float* lmax   = (const float*)d_in[4];
    const float* scale  = (const float*)d_in[5];
    const float* bias   = (const float*)d_in[6];
    float* out = (float*)d_out;

    dequant_kernel<<<4096, 256>>>(stored, sgn, lmin, lmax);
    xconv_kernel<<<512, 256>>>(x);

    static int smem_set = 0;
    if (!smem_set) {
        cudaFuncSetAttribute(gemm_kernel, cudaFuncAttributeMaxDynamicSharedMemorySize, SMEM_TOTAL);
        smem_set = 1;
    }
    dim3 grid(OUT_DIM / BN, B_DIM / BM);   // (86, 8)
    gemm_kernel<<<grid, THREADS, SMEM_TOTAL>>>(out, scale, bias);
}